// round 14
// baseline (speedup 1.0000x reference)
#include <cuda_runtime.h>
#include <cuda_bf16.h>
#include <cstdint>

#define HIDDEN 2048
#define VOCAB  32768
#define SEQ    4608
#define IGNORE (-100)

#define BM 128
#define BN 256
#define KC 256                  // fp8 elements per chunk (=256 bytes/row)
#define KP 272                  // padded row bytes (68 words % 32 = 4 -> conflict-free)
#define N_VBLK (VOCAB / BN)     // 128
#define NCH (HIDDEN / KC)       // 8
#define NTHREADS 512

#define ABYTES (BM * KP)        // 34816
#define BBYTES (BN * KP)        // 69632
#define BUFB   (ABYTES + BBYTES)
#define NSTAGE 2
#define DSMEM  (NSTAGE * BUFB)  // 208896

// ---- device scratch ----
__device__ uint8_t g_hid8[SEQ * HIDDEN];                 // e4m3(4*x)
__device__ uint8_t g_w8[(size_t)VOCAB * HIDDEN];         // e4m3(64*w)
__device__ float g_partial[(size_t)SEQ * N_VBLK];
__device__ float g_zlab[SEQ];
__device__ int   g_labels[SEQ];

// exact reference chain: u->bf16, /30->bf16, tanh->bf16 (as float)
__device__ __forceinline__ float softcap_tb(float u) {
    float uf = __bfloat162float(__float2bfloat16_rn(u));
    float d  = __bfloat162float(__float2bfloat16_rn(uf * 0.033333335071802139f));
    float s  = d * d;
    float t  = d * fmaf(s, fmaf(s, 0.13333334f, -0.33333334f), 1.0f);
    return __bfloat162float(__float2bfloat16_rn(t));
}

__device__ __forceinline__ uint32_t smem_u32(const void* p) {
    uint32_t a;
    asm("{ .reg .u64 t; cvta.to.shared.u64 t, %1; cvt.u32.u64 %0, t; }" : "=r"(a) : "l"(p));
    return a;
}
__device__ __forceinline__ void cp16(uint32_t dst, const void* src) {
    asm volatile("cp.async.cg.shared.global [%0], [%1], 16;" :: "r"(dst), "l"(src));
}
__device__ __forceinline__ void cp_commit() {
    asm volatile("cp.async.commit_group;" ::: "memory");
}
template <int N>
__device__ __forceinline__ void cp_wait() {
    asm volatile("cp.async.wait_group %0;" :: "n"(N) : "memory");
}
__device__ __forceinline__ uint16_t f2_e4m3x2(float a, float b) {
    uint16_t r;
    asm("cvt.rn.satfinite.e4m3x2.f32 %0, %1, %2;" : "=h"(r) : "f"(b), "f"(a));
    return r;
}

// ============================================================================
__global__ void prep_kernel(const int* __restrict__ ids,
                            const int* __restrict__ am,
                            float* __restrict__ out) {
    int tid = blockIdx.x * blockDim.x + threadIdx.x;
    if (tid < SEQ) {
        int lab = IGNORE;
        if (tid < SEQ - 1 && am[tid + 1] != 0) lab = ids[tid + 1];
        g_labels[tid] = lab;
    }
    if (tid == 0) *out = 0.0f;
}

// hidden fp32 -> e4m3(4x)
__global__ void hconv_kernel(const float* __restrict__ hidden) {
    int tid = blockIdx.x * blockDim.x + threadIdx.x;
    int nthreads = gridDim.x * blockDim.x;
    const int n4 = SEQ * HIDDEN / 4;
    const float4* h4 = (const float4*)hidden;
    uint32_t* o4 = (uint32_t*)g_hid8;
    for (int i = tid; i < n4; i += nthreads) {
        float4 v = h4[i];
        uint32_t lo = f2_e4m3x2(4.0f * v.x, 4.0f * v.y);
        uint32_t hi = f2_e4m3x2(4.0f * v.z, 4.0f * v.w);
        o4[i] = lo | (hi << 16);
    }
}

// W fp32 (bf16-valued) -> e4m3(64w)
__global__ void wconv_kernel(const float* __restrict__ Wf) {
    size_t tid = blockIdx.x * blockDim.x + threadIdx.x;
    size_t nthreads = (size_t)gridDim.x * blockDim.x;
    const size_t n4 = (size_t)VOCAB * HIDDEN / 4;
    const float4* w4 = (const float4*)Wf;
    uint32_t* o4 = (uint32_t*)g_w8;
    for (size_t i = tid; i < n4; i += nthreads) {
        float4 v = w4[i];
        uint32_t lo = f2_e4m3x2(64.0f * v.x, 64.0f * v.y);
        uint32_t hi = f2_e4m3x2(64.0f * v.z, 64.0f * v.w);
        o4[i] = lo | (hi << 16);
    }
}

// label-logit path in full bf16 precision, reading fp32 inputs directly
__global__ void zlab_kernel(const float* __restrict__ Wf,
                            const float* __restrict__ hidden) {
    int warp = (blockIdx.x * blockDim.x + threadIdx.x) >> 5;
    int lane = threadIdx.x & 31;
    if (warp >= SEQ) return;
    int lab = g_labels[warp];
    float z = 0.0f;
    if (lab != IGNORE) {
        const float2* xa = (const float2*)(hidden + (size_t)warp * HIDDEN);
        const float2* wb = (const float2*)(Wf + (size_t)lab * HIDDEN);
        float acc = 0.0f;
#pragma unroll 8
        for (int i = lane; i < HIDDEN / 2; i += 32) {
            float2 a = xa[i];
            float2 b = wb[i];
            float ax = __bfloat162float(__float2bfloat16_rn(a.x));
            float ay = __bfloat162float(__float2bfloat16_rn(a.y));
            acc = fmaf(ax, b.x, acc);
            acc = fmaf(ay, b.y, acc);
        }
#pragma unroll
        for (int o = 16; o > 0; o >>= 1) acc += __shfl_xor_sync(0xffffffffu, acc, o);
        z = 30.0f * softcap_tb(acc);
    }
    if (lane == 0) g_zlab[warp] = z;
}

// ============================================================================
// fp8 mma.sync GEMM: CTA 128x256, 16 warps (4M x 4N), warp tile 32x64.
// KC=256 fp8 chunks (8 total), 2-stage ring, ONE barrier + ONE wait per chunk.
// Accumulator = 256 * u (W scaled x64, x scaled x4).
// ============================================================================
__device__ __forceinline__ void mma16832(float* c, const unsigned* a, const unsigned* b) {
    asm volatile(
        "mma.sync.aligned.m16n8k32.row.col.f32.e4m3.e4m3.f32 "
        "{%0,%1,%2,%3}, {%4,%5,%6,%7}, {%8,%9}, {%0,%1,%2,%3};\n"
        : "+f"(c[0]), "+f"(c[1]), "+f"(c[2]), "+f"(c[3])
        : "r"(a[0]), "r"(a[1]), "r"(a[2]), "r"(a[3]), "r"(b[0]), "r"(b[1]));
}
__device__ __forceinline__ void ldsm_x4(unsigned& r0, unsigned& r1, unsigned& r2, unsigned& r3,
                                        unsigned addr) {
    asm volatile("ldmatrix.sync.aligned.m8n8.x4.shared.b16 {%0,%1,%2,%3}, [%4];"
                 : "=r"(r0), "=r"(r1), "=r"(r2), "=r"(r3) : "r"(addr));
}

__global__ __launch_bounds__(NTHREADS, 1)
void gemm_loss_kernel() {
    extern __shared__ char dsm[];
    __shared__ float rowsum2[BM][4];

    const int tid = threadIdx.x;
    const int m0 = blockIdx.x * BM;
    const int v0 = blockIdx.y * BN;

    const int lane = tid & 31;
    const int warp = tid >> 5;
    const int wm = warp & 3;          // 0..3: 32 M-rows
    const int wn = warp >> 2;         // 0..3: 64 N-cols
    const int g  = lane >> 2;
    const int t4 = lane & 3;
    const int q  = lane >> 3;
    const int lr = lane & 7;

    const uint32_t sbase = smem_u32(dsm);

    float acc[2][8][4];
#pragma unroll
    for (int i = 0; i < 2; i++)
#pragma unroll
        for (int j = 0; j < 8; j++)
#pragma unroll
            for (int r = 0; r < 4; r++) acc[i][j][r] = 0.0f;

    // chunk loader: A 128 rows x 256B (16 segs), B 256 rows x 256B
    auto issue_chunk = [&](int k0, int buf) {
        uint32_t abase = sbase + buf * BUFB;
        uint32_t bbase = abase + ABYTES;
#pragma unroll
        for (int l = 0; l < 4; l++) {
            int idx = tid + l * NTHREADS;
            int row = idx >> 4, seg = idx & 15;
            cp16(abase + (uint32_t)(row * KP + seg * 16),
                 g_hid8 + (size_t)(m0 + row) * HIDDEN + k0 + seg * 16);
        }
#pragma unroll
        for (int l = 0; l < 8; l++) {
            int idx = tid + l * NTHREADS;
            int row = idx >> 4, seg = idx & 15;
            cp16(bbase + (uint32_t)(row * KP + seg * 16),
                 g_w8 + (size_t)(v0 + row) * HIDDEN + k0 + seg * 16);
        }
        cp_commit();
    };

    const unsigned a_lane = ((q & 1) * 8 + lr) * KP + (q >> 1) * 16;
    const unsigned b_lane = ((q >> 1) * 8 + lr) * KP + (q & 1) * 16;

    issue_chunk(0, 0);

    for (int i = 0; i < NCH; i++) {
        const int buf = i & 1;
        cp_wait<0>();            // chunk i fully landed (this thread)
        __syncthreads();         // ...and all threads; prev compute done => buf^1 free
        if (i + 1 < NCH) issue_chunk((i + 1) * KC, buf ^ 1);   // overlaps compute below

        const unsigned as_base = sbase + buf * BUFB;
        const unsigned bs_base = as_base + ABYTES;
#pragma unroll
        for (int ks = 0; ks < 8; ks++) {          // 8 x k32
            unsigned a[2][4], b[8][2];
#pragma unroll
            for (int mt = 0; mt < 2; mt++) {
                unsigned addr = as_base + a_lane +
                                (unsigned)((wm * 32 + mt * 16) * KP + ks * 32);
                ldsm_x4(a[mt][0], a[mt][1], a[mt][2], a[mt][3], addr);
            }
#pragma unroll
            for (int p = 0; p < 4; p++) {
                unsigned addr = bs_base + b_lane +
                                (unsigned)((wn * 64 + p * 16) * KP + ks * 32);
                ldsm_x4(b[2 * p][0], b[2 * p][1], b[2 * p + 1][0], b[2 * p + 1][1], addr);
            }
#pragma unroll
            for (int mt = 0; mt < 2; mt++)
#pragma unroll
                for (int nt = 0; nt < 8; nt++)
                    mma16832(acc[mt][nt], a[mt], b[nt]);
        }
    }

    // ---- fused epilogue: u = acc/256; e = exp(30 * t_b) ----
#pragma unroll
    for (int mt = 0; mt < 2; mt++) {
        int r0 = wm * 32 + mt * 16 + g;
        int r1 = r0 + 8;
        float s0 = 0.0f, s1 = 0.0f;
#pragma unroll
        for (int nt = 0; nt < 8; nt++) {
#pragma unroll
            for (int j = 0; j < 4; j++) {
                float u = acc[mt][nt][j] * 0.00390625f;   // 1/256
                float tb = softcap_tb(u);
                float arg = tb * 43.28085122666891f;      // 30*log2(e)
                float e;
                asm("ex2.approx.f32 %0, %1;" : "=f"(e) : "f"(arg));
                if (j < 2) s0 += e; else s1 += e;
            }
        }
        s0 += __shfl_xor_sync(0xffffffffu, s0, 1);
        s0 += __shfl_xor_sync(0xffffffffu, s0, 2);
        s1 += __shfl_xor_sync(0xffffffffu, s1, 1);
        s1 += __shfl_xor_sync(0xffffffffu, s1, 2);
        if (t4 == 0) {
            rowsum2[r0][wn] = s0;
            rowsum2[r1][wn] = s1;
        }
    }
    __syncthreads();
    if (tid < BM) {
        float s = (rowsum2[tid][0] + rowsum2[tid][1]) +
                  (rowsum2[tid][2] + rowsum2[tid][3]);
        g_partial[(size_t)(m0 + tid) * N_VBLK + blockIdx.y] = s;
    }
}

// ============================================================================
__global__ void finish_kernel(float* __restrict__ out) {
    int token = blockIdx.x * blockDim.x + threadIdx.x;
    float loss = 0.0f;
    if (token < SEQ) {
        int lab = g_labels[token];
        if (lab != IGNORE) {
            const float4* p = (const float4*)(g_partial + (size_t)token * N_VBLK);
            float s = 0.0f;
#pragma unroll 8
            for (int i = 0; i < N_VBLK / 4; i++) {
                float4 v = p[i];
                s += (v.x + v.y) + (v.z + v.w);
            }
            loss = logf(s) - g_zlab[token];
        }
    }
#pragma unroll
    for (int o = 16; o > 0; o >>= 1) loss += __shfl_xor_sync(0xffffffffu, loss, o);
    __shared__ float ws[8];
    if ((threadIdx.x & 31) == 0) ws[threadIdx.x >> 5] = loss;
    __syncthreads();
    if (threadIdx.x < 8) {
        float v = ws[threadIdx.x];
#pragma unroll
        for (int o = 4; o > 0; o >>= 1) v += __shfl_xor_sync(0x000000ffu, v, o);
        if (threadIdx.x == 0) atomicAdd(out, v);
    }
}

// ============================================================================
extern "C" void kernel_launch(void* const* d_in, const int* in_sizes, int n_in,
                              void* d_out, int out_size) {
    const float* Wf     = (const float*)d_in[0];   // fp32 on device (bf16-valued)
    const float* hidden = (const float*)d_in[1];
    const int* ids      = (const int*)d_in[2];
    const int* am       = (const int*)d_in[3];
    float* out          = (float*)d_out;

    static int smem_set = 0;
    if (!smem_set) {
        cudaFuncSetAttribute(gemm_loss_kernel, cudaFuncAttributeMaxDynamicSharedMemorySize, DSMEM);
        smem_set = 1;
    }

    prep_kernel<<<(SEQ + 255) / 256, 256>>>(ids, am, out);
    hconv_kernel<<<2048, 256>>>(hidden);
    wconv_kernel<<<8192, 256>>>(Wf);
    zlab_kernel<<<(SEQ * 32 + 255) / 256, 256>>>(Wf, hidden);
    dim3 grid(SEQ / BM, VOCAB / BN);   // (36, 128)
    gemm_loss_kernel<<<grid, NTHREADS, DSMEM>>>();
    finish_kernel<<<(SEQ + 255) / 256, 256>>>(out);
}

// round 15
// speedup vs baseline: 1.0159x; 1.0159x over previous
#include <cuda_runtime.h>
#include <cuda_bf16.h>
#include <cstdint>

#define HIDDEN 2048
#define VOCAB  32768
#define SEQ    4608
#define IGNORE (-100)

#define BM 96
#define BN 256
#define KC 128                  // fp8 elements per chunk (=128 bytes/row)
#define KP 144                  // padded row bytes (36w % 32 = 4 -> conflict-free)
#define N_VBLK (VOCAB / BN)     // 128
#define NCH (HIDDEN / KC)       // 16
#define NTHREADS 384            // 12 warps = 3 per SMSP; reg cap 170

#define ABYTES (BM * KP)        // 13824
#define BBYTES (BN * KP)        // 36864
#define BUFB   (ABYTES + BBYTES)
#define NSTAGE 3
#define DSMEM  (NSTAGE * BUFB)  // 152064

// ---- device scratch ----
__device__ uint8_t g_hid8[SEQ * HIDDEN];                 // e4m3(4*x)
__device__ uint8_t g_w8[(size_t)VOCAB * HIDDEN];         // e4m3(64*w)
__device__ float g_partial[(size_t)SEQ * N_VBLK];
__device__ float g_zlab[SEQ];
__device__ int   g_labels[SEQ];

// exact reference chain: u->bf16, /30->bf16, tanh->bf16 (as float)
__device__ __forceinline__ float softcap_tb(float u) {
    float uf = __bfloat162float(__float2bfloat16_rn(u));
    float d  = __bfloat162float(__float2bfloat16_rn(uf * 0.033333335071802139f));
    float s  = d * d;
    float t  = d * fmaf(s, fmaf(s, 0.13333334f, -0.33333334f), 1.0f);
    return __bfloat162float(__float2bfloat16_rn(t));
}

__device__ __forceinline__ uint32_t smem_u32(const void* p) {
    uint32_t a;
    asm("{ .reg .u64 t; cvta.to.shared.u64 t, %1; cvt.u32.u64 %0, t; }" : "=r"(a) : "l"(p));
    return a;
}
__device__ __forceinline__ void cp16(uint32_t dst, const void* src) {
    asm volatile("cp.async.cg.shared.global [%0], [%1], 16;" :: "r"(dst), "l"(src));
}
__device__ __forceinline__ void cp_commit() {
    asm volatile("cp.async.commit_group;" ::: "memory");
}
template <int N>
__device__ __forceinline__ void cp_wait() {
    asm volatile("cp.async.wait_group %0;" :: "n"(N) : "memory");
}
__device__ __forceinline__ uint16_t f2_e4m3x2(float a, float b) {
    uint16_t r;
    asm("cvt.rn.satfinite.e4m3x2.f32 %0, %1, %2;" : "=h"(r) : "f"(b), "f"(a));
    return r;
}

// ============================================================================
__global__ void prep_kernel(const int* __restrict__ ids,
                            const int* __restrict__ am,
                            float* __restrict__ out) {
    int tid = blockIdx.x * blockDim.x + threadIdx.x;
    if (tid < SEQ) {
        int lab = IGNORE;
        if (tid < SEQ - 1 && am[tid + 1] != 0) lab = ids[tid + 1];
        g_labels[tid] = lab;
    }
    if (tid == 0) *out = 0.0f;
}

// hidden fp32 -> e4m3(4x)
__global__ void hconv_kernel(const float* __restrict__ hidden) {
    int tid = blockIdx.x * blockDim.x + threadIdx.x;
    int nthreads = gridDim.x * blockDim.x;
    const int n4 = SEQ * HIDDEN / 4;
    const float4* h4 = (const float4*)hidden;
    uint32_t* o4 = (uint32_t*)g_hid8;
    for (int i = tid; i < n4; i += nthreads) {
        float4 v = h4[i];
        uint32_t lo = f2_e4m3x2(4.0f * v.x, 4.0f * v.y);
        uint32_t hi = f2_e4m3x2(4.0f * v.z, 4.0f * v.w);
        o4[i] = lo | (hi << 16);
    }
}

// W fp32 (bf16-valued) -> e4m3(64w)
__global__ void wconv_kernel(const float* __restrict__ Wf) {
    size_t tid = blockIdx.x * blockDim.x + threadIdx.x;
    size_t nthreads = (size_t)gridDim.x * blockDim.x;
    const size_t n4 = (size_t)VOCAB * HIDDEN / 4;
    const float4* w4 = (const float4*)Wf;
    uint32_t* o4 = (uint32_t*)g_w8;
    for (size_t i = tid; i < n4; i += nthreads) {
        float4 v = w4[i];
        uint32_t lo = f2_e4m3x2(64.0f * v.x, 64.0f * v.y);
        uint32_t hi = f2_e4m3x2(64.0f * v.z, 64.0f * v.w);
        o4[i] = lo | (hi << 16);
    }
}

// label-logit path in full bf16 precision, reading fp32 inputs directly
__global__ void zlab_kernel(const float* __restrict__ Wf,
                            const float* __restrict__ hidden) {
    int warp = (blockIdx.x * blockDim.x + threadIdx.x) >> 5;
    int lane = threadIdx.x & 31;
    if (warp >= SEQ) return;
    int lab = g_labels[warp];
    float z = 0.0f;
    if (lab != IGNORE) {
        const float2* xa = (const float2*)(hidden + (size_t)warp * HIDDEN);
        const float2* wb = (const float2*)(Wf + (size_t)lab * HIDDEN);
        float acc = 0.0f;
#pragma unroll 8
        for (int i = lane; i < HIDDEN / 2; i += 32) {
            float2 a = xa[i];
            float2 b = wb[i];
            float ax = __bfloat162float(__float2bfloat16_rn(a.x));
            float ay = __bfloat162float(__float2bfloat16_rn(a.y));
            acc = fmaf(ax, b.x, acc);
            acc = fmaf(ay, b.y, acc);
        }
#pragma unroll
        for (int o = 16; o > 0; o >>= 1) acc += __shfl_xor_sync(0xffffffffu, acc, o);
        z = 30.0f * softcap_tb(acc);
    }
    if (lane == 0) g_zlab[warp] = z;
}

// ============================================================================
// fp8 mma.sync GEMM: CTA 96x256, 12 warps (3M x 4N), warp tile 32x64.
// KC=128 chunks (16), 3-stage cp.async ring, one barrier per chunk.
// 170-reg budget gives ptxas room to software-pipeline LDSM ahead of MMAs.
// Accumulator = 256 * u (W scaled x64, x scaled x4).
// ============================================================================
__device__ __forceinline__ void mma16832(float* c, const unsigned* a, const unsigned* b) {
    asm volatile(
        "mma.sync.aligned.m16n8k32.row.col.f32.e4m3.e4m3.f32 "
        "{%0,%1,%2,%3}, {%4,%5,%6,%7}, {%8,%9}, {%0,%1,%2,%3};\n"
        : "+f"(c[0]), "+f"(c[1]), "+f"(c[2]), "+f"(c[3])
        : "r"(a[0]), "r"(a[1]), "r"(a[2]), "r"(a[3]), "r"(b[0]), "r"(b[1]));
}
__device__ __forceinline__ void ldsm_x4(unsigned& r0, unsigned& r1, unsigned& r2, unsigned& r3,
                                        unsigned addr) {
    asm volatile("ldmatrix.sync.aligned.m8n8.x4.shared.b16 {%0,%1,%2,%3}, [%4];"
                 : "=r"(r0), "=r"(r1), "=r"(r2), "=r"(r3) : "r"(addr));
}

__global__ __launch_bounds__(NTHREADS, 1)
void gemm_loss_kernel() {
    extern __shared__ char dsm[];
    __shared__ float rowsum2[BM][4];

    const int tid = threadIdx.x;
    const int m0 = blockIdx.x * BM;
    const int v0 = blockIdx.y * BN;

    const int lane = tid & 31;
    const int warp = tid >> 5;        // 0..11
    const int wm = warp >> 2;         // 0..2: 32 M-rows
    const int wn = warp & 3;          // 0..3: 64 N-cols
    const int g  = lane >> 2;
    const int t4 = lane & 3;
    const int q  = lane >> 3;
    const int lr = lane & 7;

    const uint32_t sbase = smem_u32(dsm);

    float acc[2][8][4];
#pragma unroll
    for (int i = 0; i < 2; i++)
#pragma unroll
        for (int j = 0; j < 8; j++)
#pragma unroll
            for (int r = 0; r < 4; r++) acc[i][j][r] = 0.0f;

    // chunk loader: A 96 rows x 128B (8 segs = 768 cp16), B 256 rows (2048 cp16)
    auto issue_chunk = [&](int k0, int buf) {
        uint32_t abase = sbase + buf * BUFB;
        uint32_t bbase = abase + ABYTES;
#pragma unroll
        for (int l = 0; l < 2; l++) {
            int idx = tid + l * NTHREADS;          // 768 exact
            int row = idx >> 3, seg = idx & 7;
            cp16(abase + (uint32_t)(row * KP + seg * 16),
                 g_hid8 + (size_t)(m0 + row) * HIDDEN + k0 + seg * 16);
        }
#pragma unroll
        for (int l = 0; l < 6; l++) {
            int idx = tid + l * NTHREADS;
            if (idx < 2048) {
                int row = idx >> 3, seg = idx & 7;
                cp16(bbase + (uint32_t)(row * KP + seg * 16),
                     g_w8 + (size_t)(v0 + row) * HIDDEN + k0 + seg * 16);
            }
        }
        cp_commit();
    };

    const unsigned a_lane = ((q & 1) * 8 + lr) * KP + (q >> 1) * 16;
    const unsigned b_lane = ((q >> 1) * 8 + lr) * KP + (q & 1) * 16;

    issue_chunk(0, 0);
    issue_chunk(KC, 1);

    for (int i = 0; i < NCH; i++) {
        const int buf = i % NSTAGE;
        if (i == NCH - 1) cp_wait<0>(); else cp_wait<1>();
        __syncthreads();
        if (i + 2 < NCH) issue_chunk((i + 2) * KC, (i + 2) % NSTAGE);

        const unsigned as_base = sbase + buf * BUFB;
        const unsigned bs_base = as_base + ABYTES;
#pragma unroll
        for (int ks = 0; ks < 4; ks++) {          // 4 x k32
            unsigned a[2][4], b[8][2];
#pragma unroll
            for (int mt = 0; mt < 2; mt++) {
                unsigned addr = as_base + a_lane +
                                (unsigned)((wm * 32 + mt * 16) * KP + ks * 32);
                ldsm_x4(a[mt][0], a[mt][1], a[mt][2], a[mt][3], addr);
            }
#pragma unroll
            for (int p = 0; p < 4; p++) {
                unsigned addr = bs_base + b_lane +
                                (unsigned)((wn * 64 + p * 16) * KP + ks * 32);
                ldsm_x4(b[2 * p][0], b[2 * p][1], b[2 * p + 1][0], b[2 * p + 1][1], addr);
            }
#pragma unroll
            for (int mt = 0; mt < 2; mt++)
#pragma unroll
                for (int nt = 0; nt < 8; nt++)
                    mma16832(acc[mt][nt], a[mt], b[nt]);
        }
    }

    // ---- fused epilogue: u = acc/256; e = exp(30 * t_b) ----
#pragma unroll
    for (int mt = 0; mt < 2; mt++) {
        int r0 = wm * 32 + mt * 16 + g;
        int r1 = r0 + 8;
        float s0 = 0.0f, s1 = 0.0f;
#pragma unroll
        for (int nt = 0; nt < 8; nt++) {
#pragma unroll
            for (int j = 0; j < 4; j++) {
                float u = acc[mt][nt][j] * 0.00390625f;   // 1/256
                float tb = softcap_tb(u);
                float arg = tb * 43.28085122666891f;      // 30*log2(e)
                float e;
                asm("ex2.approx.f32 %0, %1;" : "=f"(e) : "f"(arg));
                if (j < 2) s0 += e; else s1 += e;
            }
        }
        s0 += __shfl_xor_sync(0xffffffffu, s0, 1);
        s0 += __shfl_xor_sync(0xffffffffu, s0, 2);
        s1 += __shfl_xor_sync(0xffffffffu, s1, 1);
        s1 += __shfl_xor_sync(0xffffffffu, s1, 2);
        if (t4 == 0) {
            rowsum2[r0][wn] = s0;
            rowsum2[r1][wn] = s1;
        }
    }
    __syncthreads();
    if (tid < BM) {
        float s = (rowsum2[tid][0] + rowsum2[tid][1]) +
                  (rowsum2[tid][2] + rowsum2[tid][3]);
        g_partial[(size_t)(m0 + tid) * N_VBLK + blockIdx.y] = s;
    }
}

// ============================================================================
__global__ void finish_kernel(float* __restrict__ out) {
    int token = blockIdx.x * blockDim.x + threadIdx.x;
    float loss = 0.0f;
    if (token < SEQ) {
        int lab = g_labels[token];
        if (lab != IGNORE) {
            const float4* p = (const float4*)(g_partial + (size_t)token * N_VBLK);
            float s = 0.0f;
#pragma unroll 8
            for (int i = 0; i < N_VBLK / 4; i++) {
                float4 v = p[i];
                s += (v.x + v.y) + (v.z + v.w);
            }
            loss = logf(s) - g_zlab[token];
        }
    }
#pragma unroll
    for (int o = 16; o > 0; o >>= 1) loss += __shfl_xor_sync(0xffffffffu, loss, o);
    __shared__ float ws[8];
    if ((threadIdx.x & 31) == 0) ws[threadIdx.x >> 5] = loss;
    __syncthreads();
    if (threadIdx.x < 8) {
        float v = ws[threadIdx.x];
#pragma unroll
        for (int o = 4; o > 0; o >>= 1) v += __shfl_xor_sync(0x000000ffu, v, o);
        if (threadIdx.x == 0) atomicAdd(out, v);
    }
}

// ============================================================================
extern "C" void kernel_launch(void* const* d_in, const int* in_sizes, int n_in,
                              void* d_out, int out_size) {
    const float* Wf     = (const float*)d_in[0];   // fp32 on device (bf16-valued)
    const float* hidden = (const float*)d_in[1];
    const int* ids      = (const int*)d_in[2];
    const int* am       = (const int*)d_in[3];
    float* out          = (float*)d_out;

    static int smem_set = 0;
    if (!smem_set) {
        cudaFuncSetAttribute(gemm_loss_kernel, cudaFuncAttributeMaxDynamicSharedMemorySize, DSMEM);
        smem_set = 1;
    }

    prep_kernel<<<(SEQ + 255) / 256, 256>>>(ids, am, out);
    hconv_kernel<<<2048, 256>>>(hidden);
    wconv_kernel<<<8192, 256>>>(Wf);
    zlab_kernel<<<(SEQ * 32 + 255) / 256, 256>>>(Wf, hidden);
    dim3 grid(SEQ / BM, VOCAB / BN);   // (48, 128)
    gemm_loss_kernel<<<grid, NTHREADS, DSMEM>>>();
    finish_kernel<<<(SEQ + 255) / 256, 256>>>(out);
}

// round 16
// speedup vs baseline: 1.0701x; 1.0534x over previous
#include <cuda_runtime.h>
#include <cuda_bf16.h>
#include <cstdint>

#define HIDDEN 2048
#define VOCAB  32768
#define SEQ    4608
#define IGNORE (-100)

#define BM 128
#define BN 128
#define KC 128                  // fp8 elements per chunk (=128 bytes/row)
#define KP 144                  // padded row bytes (36w % 32 = 4 -> conflict-free)
#define N_VBLK (VOCAB / BN)     // 256
#define NCH (HIDDEN / KC)       // 16
#define NTHREADS 256            // 8 warps; 2 CTAs/SM target

#define ABYTES (BM * KP)        // 18432
#define BBYTES (BN * KP)        // 18432
#define BUFB   (ABYTES + BBYTES)
#define NSTAGE 2
#define DSMEM  (NSTAGE * BUFB)  // 73728 -> 2 CTAs = 147KB <= 228KB

// ---- device scratch ----
__device__ uint8_t g_hid8[SEQ * HIDDEN];                 // e4m3(4*x)
__device__ uint8_t g_w8[(size_t)VOCAB * HIDDEN];         // e4m3(64*w)
__device__ float g_partial[(size_t)SEQ * N_VBLK];
__device__ float g_zlab[SEQ];
__device__ int   g_labels[SEQ];

// exact reference chain: u->bf16, /30->bf16, tanh->bf16 (as float)
__device__ __forceinline__ float softcap_tb(float u) {
    float uf = __bfloat162float(__float2bfloat16_rn(u));
    float d  = __bfloat162float(__float2bfloat16_rn(uf * 0.033333335071802139f));
    float s  = d * d;
    float t  = d * fmaf(s, fmaf(s, 0.13333334f, -0.33333334f), 1.0f);
    return __bfloat162float(__float2bfloat16_rn(t));
}

__device__ __forceinline__ uint32_t smem_u32(const void* p) {
    uint32_t a;
    asm("{ .reg .u64 t; cvta.to.shared.u64 t, %1; cvt.u32.u64 %0, t; }" : "=r"(a) : "l"(p));
    return a;
}
__device__ __forceinline__ void cp16(uint32_t dst, const void* src) {
    asm volatile("cp.async.cg.shared.global [%0], [%1], 16;" :: "r"(dst), "l"(src));
}
__device__ __forceinline__ void cp_commit() {
    asm volatile("cp.async.commit_group;" ::: "memory");
}
template <int N>
__device__ __forceinline__ void cp_wait() {
    asm volatile("cp.async.wait_group %0;" :: "n"(N) : "memory");
}
__device__ __forceinline__ uint16_t f2_e4m3x2(float a, float b) {
    uint16_t r;
    asm("cvt.rn.satfinite.e4m3x2.f32 %0, %1, %2;" : "=h"(r) : "f"(b), "f"(a));
    return r;
}

// ============================================================================
__global__ void prep_kernel(const int* __restrict__ ids,
                            const int* __restrict__ am,
                            float* __restrict__ out) {
    int tid = blockIdx.x * blockDim.x + threadIdx.x;
    if (tid < SEQ) {
        int lab = IGNORE;
        if (tid < SEQ - 1 && am[tid + 1] != 0) lab = ids[tid + 1];
        g_labels[tid] = lab;
    }
    if (tid == 0) *out = 0.0f;
}

// hidden fp32 -> e4m3(4x)
__global__ void hconv_kernel(const float* __restrict__ hidden) {
    int tid = blockIdx.x * blockDim.x + threadIdx.x;
    int nthreads = gridDim.x * blockDim.x;
    const int n4 = SEQ * HIDDEN / 4;
    const float4* h4 = (const float4*)hidden;
    uint32_t* o4 = (uint32_t*)g_hid8;
    for (int i = tid; i < n4; i += nthreads) {
        float4 v = h4[i];
        uint32_t lo = f2_e4m3x2(4.0f * v.x, 4.0f * v.y);
        uint32_t hi = f2_e4m3x2(4.0f * v.z, 4.0f * v.w);
        o4[i] = lo | (hi << 16);
    }
}

// W fp32 (bf16-valued) -> e4m3(64w)
__global__ void wconv_kernel(const float* __restrict__ Wf) {
    size_t tid = blockIdx.x * blockDim.x + threadIdx.x;
    size_t nthreads = (size_t)gridDim.x * blockDim.x;
    const size_t n4 = (size_t)VOCAB * HIDDEN / 4;
    const float4* w4 = (const float4*)Wf;
    uint32_t* o4 = (uint32_t*)g_w8;
    for (size_t i = tid; i < n4; i += nthreads) {
        float4 v = w4[i];
        uint32_t lo = f2_e4m3x2(64.0f * v.x, 64.0f * v.y);
        uint32_t hi = f2_e4m3x2(64.0f * v.z, 64.0f * v.w);
        o4[i] = lo | (hi << 16);
    }
}

// label-logit path in full bf16 precision, reading fp32 inputs directly
__global__ void zlab_kernel(const float* __restrict__ Wf,
                            const float* __restrict__ hidden) {
    int warp = (blockIdx.x * blockDim.x + threadIdx.x) >> 5;
    int lane = threadIdx.x & 31;
    if (warp >= SEQ) return;
    int lab = g_labels[warp];
    float z = 0.0f;
    if (lab != IGNORE) {
        const float2* xa = (const float2*)(hidden + (size_t)warp * HIDDEN);
        const float2* wb = (const float2*)(Wf + (size_t)lab * HIDDEN);
        float acc = 0.0f;
#pragma unroll 8
        for (int i = lane; i < HIDDEN / 2; i += 32) {
            float2 a = xa[i];
            float2 b = wb[i];
            float ax = __bfloat162float(__float2bfloat16_rn(a.x));
            float ay = __bfloat162float(__float2bfloat16_rn(a.y));
            acc = fmaf(ax, b.x, acc);
            acc = fmaf(ay, b.y, acc);
        }
#pragma unroll
        for (int o = 16; o > 0; o >>= 1) acc += __shfl_xor_sync(0xffffffffu, acc, o);
        z = 30.0f * softcap_tb(acc);
    }
    if (lane == 0) g_zlab[warp] = z;
}

// ============================================================================
// fp8 mma.sync GEMM: CTA 128x128, 8 warps (4M x 2N), warp tile 32x64.
// 2 CTAs co-resident per SM: cross-CTA MMA/barrier overlap.
// KC=128 chunks (16), 2-stage ring, one cp_wait + one barrier per chunk.
// Accumulator = 256 * u (W scaled x64, x scaled x4).
// ============================================================================
__device__ __forceinline__ void mma16832(float* c, const unsigned* a, const unsigned* b) {
    asm volatile(
        "mma.sync.aligned.m16n8k32.row.col.f32.e4m3.e4m3.f32 "
        "{%0,%1,%2,%3}, {%4,%5,%6,%7}, {%8,%9}, {%0,%1,%2,%3};\n"
        : "+f"(c[0]), "+f"(c[1]), "+f"(c[2]), "+f"(c[3])
        : "r"(a[0]), "r"(a[1]), "r"(a[2]), "r"(a[3]), "r"(b[0]), "r"(b[1]));
}
__device__ __forceinline__ void ldsm_x4(unsigned& r0, unsigned& r1, unsigned& r2, unsigned& r3,
                                        unsigned addr) {
    asm volatile("ldmatrix.sync.aligned.m8n8.x4.shared.b16 {%0,%1,%2,%3}, [%4];"
                 : "=r"(r0), "=r"(r1), "=r"(r2), "=r"(r3) : "r"(addr));
}

__global__ __launch_bounds__(NTHREADS, 2)
void gemm_loss_kernel() {
    extern __shared__ char dsm[];
    __shared__ float rowsum2[BM][2];

    const int tid = threadIdx.x;
    const int m0 = blockIdx.x * BM;
    const int v0 = blockIdx.y * BN;

    const int lane = tid & 31;
    const int warp = tid >> 5;        // 0..7
    const int wm = warp >> 1;         // 0..3: 32 M-rows
    const int wn = warp & 1;          // 0..1: 64 N-cols
    const int g  = lane >> 2;
    const int t4 = lane & 3;
    const int q  = lane >> 3;
    const int lr = lane & 7;

    const uint32_t sbase = smem_u32(dsm);

    float acc[2][8][4];
#pragma unroll
    for (int i = 0; i < 2; i++)
#pragma unroll
        for (int j = 0; j < 8; j++)
#pragma unroll
            for (int r = 0; r < 4; r++) acc[i][j][r] = 0.0f;

    // chunk loader: A 128 rows x 128B (8 segs) = 1024 cp16; B same. 8/thread.
    auto issue_chunk = [&](int k0, int buf) {
        uint32_t abase = sbase + buf * BUFB;
        uint32_t bbase = abase + ABYTES;
#pragma unroll
        for (int l = 0; l < 4; l++) {
            int idx = tid + l * NTHREADS;
            int row = idx >> 3, seg = idx & 7;
            cp16(abase + (uint32_t)(row * KP + seg * 16),
                 g_hid8 + (size_t)(m0 + row) * HIDDEN + k0 + seg * 16);
        }
#pragma unroll
        for (int l = 0; l < 4; l++) {
            int idx = tid + l * NTHREADS;
            int row = idx >> 3, seg = idx & 7;
            cp16(bbase + (uint32_t)(row * KP + seg * 16),
                 g_w8 + (size_t)(v0 + row) * HIDDEN + k0 + seg * 16);
        }
        cp_commit();
    };

    const unsigned a_lane = ((q & 1) * 8 + lr) * KP + (q >> 1) * 16;
    const unsigned b_lane = ((q >> 1) * 8 + lr) * KP + (q & 1) * 16;

    issue_chunk(0, 0);

    for (int i = 0; i < NCH; i++) {
        const int buf = i & 1;
        cp_wait<0>();            // chunk i landed (this thread's view)
        __syncthreads();         // all threads; buf^1 consumers finished at i-1
        if (i + 1 < NCH) issue_chunk((i + 1) * KC, buf ^ 1);   // overlaps compute

        const unsigned as_base = sbase + buf * BUFB;
        const unsigned bs_base = as_base + ABYTES;
#pragma unroll
        for (int ks = 0; ks < 4; ks++) {          // 4 x k32
            unsigned a[2][4], b[8][2];
#pragma unroll
            for (int mt = 0; mt < 2; mt++) {
                unsigned addr = as_base + a_lane +
                                (unsigned)((wm * 32 + mt * 16) * KP + ks * 32);
                ldsm_x4(a[mt][0], a[mt][1], a[mt][2], a[mt][3], addr);
            }
#pragma unroll
            for (int p = 0; p < 4; p++) {
                unsigned addr = bs_base + b_lane +
                                (unsigned)((wn * 64 + p * 16) * KP + ks * 32);
                ldsm_x4(b[2 * p][0], b[2 * p][1], b[2 * p + 1][0], b[2 * p + 1][1], addr);
            }
#pragma unroll
            for (int mt = 0; mt < 2; mt++)
#pragma unroll
                for (int nt = 0; nt < 8; nt++)
                    mma16832(acc[mt][nt], a[mt], b[nt]);
        }
    }

    // ---- fused epilogue: u = acc/256; e = exp(30 * t_b) ----
#pragma unroll
    for (int mt = 0; mt < 2; mt++) {
        int r0 = wm * 32 + mt * 16 + g;
        int r1 = r0 + 8;
        float s0 = 0.0f, s1 = 0.0f;
#pragma unroll
        for (int nt = 0; nt < 8; nt++) {
#pragma unroll
            for (int j = 0; j < 4; j++) {
                float u = acc[mt][nt][j] * 0.00390625f;   // 1/256
                float tb = softcap_tb(u);
                float arg = tb * 43.28085122666891f;      // 30*log2(e)
                float e;
                asm("ex2.approx.f32 %0, %1;" : "=f"(e) : "f"(arg));
                if (j < 2) s0 += e; else s1 += e;
            }
        }
        s0 += __shfl_xor_sync(0xffffffffu, s0, 1);
        s0 += __shfl_xor_sync(0xffffffffu, s0, 2);
        s1 += __shfl_xor_sync(0xffffffffu, s1, 1);
        s1 += __shfl_xor_sync(0xffffffffu, s1, 2);
        if (t4 == 0) {
            rowsum2[r0][wn] = s0;
            rowsum2[r1][wn] = s1;
        }
    }
    __syncthreads();
    if (tid < BM)
        g_partial[(size_t)(m0 + tid) * N_VBLK + blockIdx.y] =
            rowsum2[tid][0] + rowsum2[tid][1];
}

// ============================================================================
__global__ void finish_kernel(float* __restrict__ out) {
    int token = blockIdx.x * blockDim.x + threadIdx.x;
    float loss = 0.0f;
    if (token < SEQ) {
        int lab = g_labels[token];
        if (lab != IGNORE) {
            const float4* p = (const float4*)(g_partial + (size_t)token * N_VBLK);
            float s = 0.0f;
#pragma unroll 8
            for (int i = 0; i < N_VBLK / 4; i++) {
                float4 v = p[i];
                s += (v.x + v.y) + (v.z + v.w);
            }
            loss = logf(s) - g_zlab[token];
        }
    }
#pragma unroll
    for (int o = 16; o > 0; o >>= 1) loss += __shfl_xor_sync(0xffffffffu, loss, o);
    __shared__ float ws[8];
    if ((threadIdx.x & 31) == 0) ws[threadIdx.x >> 5] = loss;
    __syncthreads();
    if (threadIdx.x < 8) {
        float v = ws[threadIdx.x];
#pragma unroll
        for (int o = 4; o > 0; o >>= 1) v += __shfl_xor_sync(0x000000ffu, v, o);
        if (threadIdx.x == 0) atomicAdd(out, v);
    }
}

// ============================================================================
extern "C" void kernel_launch(void* const* d_in, const int* in_sizes, int n_in,
                              void* d_out, int out_size) {
    const float* Wf     = (const float*)d_in[0];   // fp32 on device (bf16-valued)
    const float* hidden = (const float*)d_in[1];
    const int* ids      = (const int*)d_in[2];
    const int* am       = (const int*)d_in[3];
    float* out          = (float*)d_out;

    static int smem_set = 0;
    if (!smem_set) {
        cudaFuncSetAttribute(gemm_loss_kernel, cudaFuncAttributeMaxDynamicSharedMemorySize, DSMEM);
        smem_set = 1;
    }

    prep_kernel<<<(SEQ + 255) / 256, 256>>>(ids, am, out);
    hconv_kernel<<<2048, 256>>>(hidden);
    wconv_kernel<<<8192, 256>>>(Wf);
    zlab_kernel<<<(SEQ * 32 + 255) / 256, 256>>>(Wf, hidden);
    dim3 grid(SEQ / BM, VOCAB / BN);   // (36, 256)
    gemm_loss_kernel<<<grid, NTHREADS, DSMEM>>>();
    finish_kernel<<<(SEQ + 255) / 256, 256>>>(out);
}

// round 17
// speedup vs baseline: 1.1334x; 1.0592x over previous
#include <cuda_runtime.h>
#include <cuda_bf16.h>
#include <cuda_fp16.h>
#include <cstdint>

#define HIDDEN 2048
#define VOCAB  32768
#define SEQ    4608
#define IGNORE (-100)

#define BM 128
#define BN 128
#define KC 128                  // fp8 elements per chunk (=128 bytes/row)
#define KP 144                  // padded row bytes (36w % 32 = 4 -> conflict-free)
#define N_VBLK (VOCAB / BN)     // 256
#define NCH (HIDDEN / KC)       // 16
#define NTHREADS 256            // 8 warps; 2 CTAs/SM

#define ABYTES (BM * KP)        // 18432
#define BBYTES (BN * KP)        // 18432
#define BUFB   (ABYTES + BBYTES)
#define NSTAGE 2
#define DSMEM  (NSTAGE * BUFB)  // 73728 -> 2 CTAs = 147KB

// ---- device scratch ----
__device__ uint8_t g_hid8[SEQ * HIDDEN];                 // e4m3(4*x)
__device__ uint8_t g_w8[(size_t)VOCAB * HIDDEN];         // e4m3(64*w)
__device__ float g_partial[(size_t)SEQ * N_VBLK];
__device__ float g_zlab[SEQ];
__device__ int   g_labels[SEQ];

// exact reference chain: u->bf16, /30->bf16, tanh->bf16 (as float)
__device__ __forceinline__ float softcap_tb(float u) {
    float uf = __bfloat162float(__float2bfloat16_rn(u));
    float d  = __bfloat162float(__float2bfloat16_rn(uf * 0.033333335071802139f));
    float s  = d * d;
    float t  = d * fmaf(s, fmaf(s, 0.13333334f, -0.33333334f), 1.0f);
    return __bfloat162float(__float2bfloat16_rn(t));
}

__device__ __forceinline__ uint32_t smem_u32(const void* p) {
    uint32_t a;
    asm("{ .reg .u64 t; cvta.to.shared.u64 t, %1; cvt.u32.u64 %0, t; }" : "=r"(a) : "l"(p));
    return a;
}
__device__ __forceinline__ void cp16(uint32_t dst, const void* src) {
    asm volatile("cp.async.cg.shared.global [%0], [%1], 16;" :: "r"(dst), "l"(src));
}
__device__ __forceinline__ void cp_commit() {
    asm volatile("cp.async.commit_group;" ::: "memory");
}
template <int N>
__device__ __forceinline__ void cp_wait() {
    asm volatile("cp.async.wait_group %0;" :: "n"(N) : "memory");
}
__device__ __forceinline__ uint16_t f2_e4m3x2(float a, float b) {
    uint16_t r;
    asm("cvt.rn.satfinite.e4m3x2.f32 %0, %1, %2;" : "=h"(r) : "f"(b), "f"(a));
    return r;
}

// ============================================================================
__global__ void prep_kernel(const int* __restrict__ ids,
                            const int* __restrict__ am,
                            float* __restrict__ out) {
    int tid = blockIdx.x * blockDim.x + threadIdx.x;
    if (tid < SEQ) {
        int lab = IGNORE;
        if (tid < SEQ - 1 && am[tid + 1] != 0) lab = ids[tid + 1];
        g_labels[tid] = lab;
    }
    if (tid == 0) *out = 0.0f;
}

// hidden fp32 -> e4m3(4x)
__global__ void hconv_kernel(const float* __restrict__ hidden) {
    int tid = blockIdx.x * blockDim.x + threadIdx.x;
    int nthreads = gridDim.x * blockDim.x;
    const int n4 = SEQ * HIDDEN / 4;
    const float4* h4 = (const float4*)hidden;
    uint32_t* o4 = (uint32_t*)g_hid8;
    for (int i = tid; i < n4; i += nthreads) {
        float4 v = h4[i];
        uint32_t lo = f2_e4m3x2(4.0f * v.x, 4.0f * v.y);
        uint32_t hi = f2_e4m3x2(4.0f * v.z, 4.0f * v.w);
        o4[i] = lo | (hi << 16);
    }
}

// W fp32 (bf16-valued) -> e4m3(64w)
__global__ void wconv_kernel(const float* __restrict__ Wf) {
    size_t tid = blockIdx.x * blockDim.x + threadIdx.x;
    size_t nthreads = (size_t)gridDim.x * blockDim.x;
    const size_t n4 = (size_t)VOCAB * HIDDEN / 4;
    const float4* w4 = (const float4*)Wf;
    uint32_t* o4 = (uint32_t*)g_w8;
    for (size_t i = tid; i < n4; i += nthreads) {
        float4 v = w4[i];
        uint32_t lo = f2_e4m3x2(64.0f * v.x, 64.0f * v.y);
        uint32_t hi = f2_e4m3x2(64.0f * v.z, 64.0f * v.w);
        o4[i] = lo | (hi << 16);
    }
}

// label-logit path in full bf16 precision, reading fp32 inputs directly
__global__ void zlab_kernel(const float* __restrict__ Wf,
                            const float* __restrict__ hidden) {
    int warp = (blockIdx.x * blockDim.x + threadIdx.x) >> 5;
    int lane = threadIdx.x & 31;
    if (warp >= SEQ) return;
    int lab = g_labels[warp];
    float z = 0.0f;
    if (lab != IGNORE) {
        const float2* xa = (const float2*)(hidden + (size_t)warp * HIDDEN);
        const float2* wb = (const float2*)(Wf + (size_t)lab * HIDDEN);
        float acc = 0.0f;
#pragma unroll 8
        for (int i = lane; i < HIDDEN / 2; i += 32) {
            float2 a = xa[i];
            float2 b = wb[i];
            float ax = __bfloat162float(__float2bfloat16_rn(a.x));
            float ay = __bfloat162float(__float2bfloat16_rn(a.y));
            acc = fmaf(ax, b.x, acc);
            acc = fmaf(ay, b.y, acc);
        }
#pragma unroll
        for (int o = 16; o > 0; o >>= 1) acc += __shfl_xor_sync(0xffffffffu, acc, o);
        z = 30.0f * softcap_tb(acc);
    }
    if (lane == 0) g_zlab[warp] = z;
}

// ============================================================================
// fp8 mma.sync GEMM with F16 ACCUMULATORS (tests 2x fp8 rate).
// CTA 128x128, 8 warps (4M x 2N), warp tile 32x64, 2 CTAs/SM.
// KC=128 chunks (16), 2-stage ring, one cp_wait + one barrier per chunk.
// Accumulator = 256 * u in f16 (W scaled x64, x scaled x4).
// ============================================================================
__device__ __forceinline__ void mma16832h(uint32_t* c, const unsigned* a, const unsigned* b) {
    asm volatile(
        "mma.sync.aligned.m16n8k32.row.col.f16.e4m3.e4m3.f16 "
        "{%0,%1}, {%2,%3,%4,%5}, {%6,%7}, {%0,%1};\n"
        : "+r"(c[0]), "+r"(c[1])
        : "r"(a[0]), "r"(a[1]), "r"(a[2]), "r"(a[3]), "r"(b[0]), "r"(b[1]));
}
__device__ __forceinline__ void ldsm_x4(unsigned& r0, unsigned& r1, unsigned& r2, unsigned& r3,
                                        unsigned addr) {
    asm volatile("ldmatrix.sync.aligned.m8n8.x4.shared.b16 {%0,%1,%2,%3}, [%4];"
                 : "=r"(r0), "=r"(r1), "=r"(r2), "=r"(r3) : "r"(addr));
}

__global__ __launch_bounds__(NTHREADS, 2)
void gemm_loss_kernel() {
    extern __shared__ char dsm[];
    __shared__ float rowsum2[BM][2];

    const int tid = threadIdx.x;
    const int m0 = blockIdx.x * BM;
    const int v0 = blockIdx.y * BN;

    const int lane = tid & 31;
    const int warp = tid >> 5;        // 0..7
    const int wm = warp >> 1;         // 0..3: 32 M-rows
    const int wn = warp & 1;          // 0..1: 64 N-cols
    const int g  = lane >> 2;
    const int t4 = lane & 3;
    const int q  = lane >> 3;
    const int lr = lane & 7;

    const uint32_t sbase = smem_u32(dsm);

    uint32_t acc[2][8][2];            // f16x2 accumulators
#pragma unroll
    for (int i = 0; i < 2; i++)
#pragma unroll
        for (int j = 0; j < 8; j++) {
            acc[i][j][0] = 0u;
            acc[i][j][1] = 0u;
        }

    // chunk loader: A 128 rows x 128B (8 segs) = 1024 cp16; B same. 8/thread.
    auto issue_chunk = [&](int k0, int buf) {
        uint32_t abase = sbase + buf * BUFB;
        uint32_t bbase = abase + ABYTES;
#pragma unroll
        for (int l = 0; l < 4; l++) {
            int idx = tid + l * NTHREADS;
            int row = idx >> 3, seg = idx & 7;
            cp16(abase + (uint32_t)(row * KP + seg * 16),
                 g_hid8 + (size_t)(m0 + row) * HIDDEN + k0 + seg * 16);
        }
#pragma unroll
        for (int l = 0; l < 4; l++) {
            int idx = tid + l * NTHREADS;
            int row = idx >> 3, seg = idx & 7;
            cp16(bbase + (uint32_t)(row * KP + seg * 16),
                 g_w8 + (size_t)(v0 + row) * HIDDEN + k0 + seg * 16);
        }
        cp_commit();
    };

    const unsigned a_lane = ((q & 1) * 8 + lr) * KP + (q >> 1) * 16;
    const unsigned b_lane = ((q >> 1) * 8 + lr) * KP + (q & 1) * 16;

    issue_chunk(0, 0);

    for (int i = 0; i < NCH; i++) {
        const int buf = i & 1;
        cp_wait<0>();
        __syncthreads();
        if (i + 1 < NCH) issue_chunk((i + 1) * KC, buf ^ 1);

        const unsigned as_base = sbase + buf * BUFB;
        const unsigned bs_base = as_base + ABYTES;
#pragma unroll
        for (int ks = 0; ks < 4; ks++) {          // 4 x k32
            unsigned a[2][4], b[8][2];
#pragma unroll
            for (int mt = 0; mt < 2; mt++) {
                unsigned addr = as_base + a_lane +
                                (unsigned)((wm * 32 + mt * 16) * KP + ks * 32);
                ldsm_x4(a[mt][0], a[mt][1], a[mt][2], a[mt][3], addr);
            }
#pragma unroll
            for (int p = 0; p < 4; p++) {
                unsigned addr = bs_base + b_lane +
                                (unsigned)((wn * 64 + p * 16) * KP + ks * 32);
                ldsm_x4(b[2 * p][0], b[2 * p][1], b[2 * p + 1][0], b[2 * p + 1][1], addr);
            }
#pragma unroll
            for (int mt = 0; mt < 2; mt++)
#pragma unroll
                for (int nt = 0; nt < 8; nt++)
                    mma16832h(acc[mt][nt], a[mt], b[nt]);
        }
    }

    // ---- fused epilogue: u = acc/256; e = exp(30 * t_b) ----
#pragma unroll
    for (int mt = 0; mt < 2; mt++) {
        int r0 = wm * 32 + mt * 16 + g;
        int r1 = r0 + 8;
        float s0 = 0.0f, s1 = 0.0f;
#pragma unroll
        for (int nt = 0; nt < 8; nt++) {
            // reg0 holds {c0,c1} (row g), reg1 holds {c2,c3} (row g+8)
            float2 lo = __half22float2(*(const __half2*)&acc[mt][nt][0]);
            float2 hi = __half22float2(*(const __half2*)&acc[mt][nt][1]);
#pragma unroll
            for (int j = 0; j < 4; j++) {
                float raw = (j == 0) ? lo.x : (j == 1) ? lo.y : (j == 2) ? hi.x : hi.y;
                float u = raw * 0.00390625f;              // 1/256
                float tb = softcap_tb(u);
                float arg = tb * 43.28085122666891f;      // 30*log2(e)
                float e;
                asm("ex2.approx.f32 %0, %1;" : "=f"(e) : "f"(arg));
                if (j < 2) s0 += e; else s1 += e;
            }
        }
        s0 += __shfl_xor_sync(0xffffffffu, s0, 1);
        s0 += __shfl_xor_sync(0xffffffffu, s0, 2);
        s1 += __shfl_xor_sync(0xffffffffu, s1, 1);
        s1 += __shfl_xor_sync(0xffffffffu, s1, 2);
        if (t4 == 0) {
            rowsum2[r0][wn] = s0;
            rowsum2[r1][wn] = s1;
        }
    }
    __syncthreads();
    if (tid < BM)
        g_partial[(size_t)(m0 + tid) * N_VBLK + blockIdx.y] =
            rowsum2[tid][0] + rowsum2[tid][1];
}

// ============================================================================
__global__ void finish_kernel(float* __restrict__ out) {
    int token = blockIdx.x * blockDim.x + threadIdx.x;
    float loss = 0.0f;
    if (token < SEQ) {
        int lab = g_labels[token];
        if (lab != IGNORE) {
            const float4* p = (const float4*)(g_partial + (size_t)token * N_VBLK);
            float s = 0.0f;
#pragma unroll 8
            for (int i = 0; i < N_VBLK / 4; i++) {
                float4 v = p[i];
                s += (v.x + v.y) + (v.z + v.w);
            }
            loss = logf(s) - g_zlab[token];
        }
    }
#pragma unroll
    for (int o = 16; o > 0; o >>= 1) loss += __shfl_xor_sync(0xffffffffu, loss, o);
    __shared__ float ws[8];
    if ((threadIdx.x & 31) == 0) ws[threadIdx.x >> 5] = loss;
    __syncthreads();
    if (threadIdx.x < 8) {
        float v = ws[threadIdx.x];
#pragma unroll
        for (int o = 4; o > 0; o >>= 1) v += __shfl_xor_sync(0x000000ffu, v, o);
        if (threadIdx.x == 0) atomicAdd(out, v);
    }
}

// ============================================================================
extern "C" void kernel_launch(void* const* d_in, const int* in_sizes, int n_in,
                              void* d_out, int out_size) {
    const float* Wf     = (const float*)d_in[0];   // fp32 on device (bf16-valued)
    const float* hidden = (const float*)d_in[1];
    const int* ids      = (const int*)d_in[2];
    const int* am       = (const int*)d_in[3];
    float* out          = (float*)d_out;

    static int smem_set = 0;
    if (!smem_set) {
        cudaFuncSetAttribute(gemm_loss_kernel, cudaFuncAttributeMaxDynamicSharedMemorySize, DSMEM);
        smem_set = 1;
    }

    prep_kernel<<<(SEQ + 255) / 256, 256>>>(ids, am, out);
    hconv_kernel<<<2048, 256>>>(hidden);
    wconv_kernel<<<8192, 256>>>(Wf);
    zlab_kernel<<<(SEQ * 32 + 255) / 256, 256>>>(Wf, hidden);
    dim3 grid(SEQ / BM, VOCAB / BN);   // (36, 256)
    gemm_loss_kernel<<<grid, NTHREADS, DSMEM>>>();
    finish_kernel<<<(SEQ + 255) / 256, 256>>>(out);
}